// round 4
// baseline (speedup 1.0000x reference)
#include <cuda_runtime.h>
#include <math.h>

// Problem constants
#define BB 16
#define TT 32
#define HH 40
#define WW 40
#define FF 40
#define NG 160   // 4*F gate channels

// ---------------------------------------------------------------------------
// Static device scratch (no cudaMalloc allowed).
//   g_seq0/g_seq1 : ping-pong per-layer output sequences [B,T,H,W,F]
//   g_h[2]        : double-buffered hidden state [B,H,W,F]
//   g_c           : cell state [B,H,W,F] (updated in place, block-private)
// ---------------------------------------------------------------------------
__device__ float g_seq0[BB * TT * HH * WW * FF];
__device__ float g_seq1[BB * TT * HH * WW * FF];
__device__ float g_hbuf[2][BB * HH * WW * FF];
__device__ float g_cbuf[BB * HH * WW * FF];

__device__ __forceinline__ float hsig(float x) {
    // keras hard_sigmoid: clip(0.2x+0.5, 0, 1)
    return fminf(fmaxf(0.2f * x + 0.5f, 0.0f), 1.0f);
}

// ---------------------------------------------------------------------------
// One ConvLSTM timestep for one layer.
// Grid: (HH, BB)  -> block handles one image row (b, y): 40 pixels.
// Block: 128 threads. GEMM tile: M=40 px, N=160 gates, K=9*(CIN+FF).
// Thread tile: 10 px x 5 ch  (channel co = lane + 32*j -> coalesced B loads,
// A loads are warp broadcasts, float4-vectorized over K).
// SMEM: sIn[3][42][C2P] input tile (x ++ h concatenated, zero halo),
//       sW[40*160] weight chunk (one tap, 40 input channels), reused as z.
// ---------------------------------------------------------------------------
template <int CIN>
__global__ __launch_bounds__(128) void lstm_step(
    const float* __restrict__ xseq,   // [B,T,H,W,CIN]
    const float* __restrict__ hin,    // [B,H,W,F]   (ignored if first)
    float* __restrict__ hout,         // [B,H,W,F]
    float* __restrict__ cst,          // [B,H,W,F]   in/out
    const float* __restrict__ Wx,     // [9,CIN,160]
    const float* __restrict__ Wh,     // [9,F,160]
    const float* __restrict__ bias,   // [160]
    const float* __restrict__ bng,    // [F] gamma
    const float* __restrict__ bnb,    // [F] beta
    const float* __restrict__ bnm,    // [F] mean
    const float* __restrict__ bnv,    // [F] var
    float* __restrict__ yout,         // [B,T,H,W,F] BN(h)
    int t, int first)
{
    constexpr int HOFF = (CIN + 3) & ~3;   // h channels start (4 or 40)
    constexpr int C2P  = HOFF + FF;        // padded concat channels (44 or 80)
    constexpr int INROW = 42;              // 40 + halo

    extern __shared__ float smem[];
    float* sIn = smem;                     // [3][INROW][C2P]
    float* sW  = smem + 3 * INROW * C2P;   // [40*160], reused as z buffer

    const int tid = threadIdx.x;
    const int y   = blockIdx.x;
    const int b   = blockIdx.y;
    const int n   = tid & 31;   // lane -> base output channel
    const int mt  = tid >> 5;   // 0..3 -> pixel group (10 px each)

    // ---- zero the input tile (halo + channel padding) ----
    for (int i = tid; i < 3 * INROW * C2P; i += 128) sIn[i] = 0.0f;
    __syncthreads();

    // ---- fill x part ----
    if (CIN == 1) {
        for (int i = tid; i < 3 * WW; i += 128) {
            int r = i / WW, x = i % WW;
            int gy = y + r - 1;
            if (gy >= 0 && gy < HH)
                sIn[(r * INROW + x + 1) * C2P] =
                    xseq[((b * TT + t) * HH + gy) * WW + x];
        }
    } else {
        constexpr int NC4 = CIN / 4;
        for (int i = tid; i < 3 * WW * NC4; i += 128) {
            int c4 = i % NC4;
            int rest = i / NC4;
            int x = rest % WW, r = rest / WW;
            int gy = y + r - 1;
            if (gy >= 0 && gy < HH) {
                float4 v = *(const float4*)&xseq[(((b * TT + t) * HH + gy) * WW + x) * CIN + c4 * 4];
                *(float4*)&sIn[(r * INROW + x + 1) * C2P + c4 * 4] = v;
            }
        }
    }

    // ---- fill h part (skip at t==0: h=0) ----
    if (!first) {
        for (int i = tid; i < 3 * WW * (FF / 4); i += 128) {
            int c4 = i % (FF / 4);
            int rest = i / (FF / 4);
            int x = rest % WW, r = rest / WW;
            int gy = y + r - 1;
            if (gy >= 0 && gy < HH) {
                float4 v = *(const float4*)&hin[((b * HH + gy) * WW + x) * FF + c4 * 4];
                *(float4*)&sIn[(r * INROW + x + 1) * C2P + HOFF + c4 * 4] = v;
            }
        }
    }

    // ---- accumulators initialized to bias ----
    float acc[10][5];
#pragma unroll
    for (int j = 0; j < 5; j++) {
        float bj = bias[n + 32 * j];
#pragma unroll
        for (int i = 0; i < 10; i++) acc[i][j] = bj;
    }

    // ---- main loop: 9 taps x {x-chunk, h-chunk} ----
#pragma unroll 1
    for (int tap = 0; tap < 9; ++tap) {
        const int dy = tap / 3, dx = tap % 3;
#pragma unroll 1
        for (int part = 0; part < 2; ++part) {
            if (part == 1 && first) continue;  // uniform across block
            const float* src = (part == 0) ? (Wx + tap * CIN * NG) : (Wh + tap * FF * NG);
            const int len    = (part == 0) ? CIN : FF;
            const int cbase  = (part == 0) ? 0 : HOFF;

            __syncthreads();   // previous chunk fully consumed
            for (int p = tid; p < len * (NG / 4); p += 128)
                ((float4*)sW)[p] = ((const float4*)src)[p];
            __syncthreads();

            // pixel m reads smem column m+dx (halo offset folded in)
            const float* abase = sIn + (dy * INROW + dx) * C2P + cbase;
            const int kmain = len & ~3;

#pragma unroll 1
            for (int kk = 0; kk < kmain; kk += 4) {
                float4 a[10];
#pragma unroll
                for (int i = 0; i < 10; i++)
                    a[i] = *(const float4*)(abase + (mt * 10 + i) * C2P + kk);
#pragma unroll
                for (int l = 0; l < 4; l++) {
                    float bv[5];
#pragma unroll
                    for (int j = 0; j < 5; j++)
                        bv[j] = sW[(kk + l) * NG + n + 32 * j];
#pragma unroll
                    for (int i = 0; i < 10; i++) {
                        float av = (l == 0) ? a[i].x : (l == 1) ? a[i].y
                                 : (l == 2) ? a[i].z : a[i].w;
#pragma unroll
                        for (int j = 0; j < 5; j++) acc[i][j] += av * bv[j];
                    }
                }
            }
            // remainder (only CIN=1 x-chunk)
            for (int kk = kmain; kk < len; kk++) {
                float bv[5];
#pragma unroll
                for (int j = 0; j < 5; j++)
                    bv[j] = sW[kk * NG + n + 32 * j];
#pragma unroll
                for (int i = 0; i < 10; i++) {
                    float av = abase[(mt * 10 + i) * C2P + kk];
#pragma unroll
                    for (int j = 0; j < 5; j++) acc[i][j] += av * bv[j];
                }
            }
        }
    }

    // ---- z to smem (reuse sW), then gate math ----
    __syncthreads();
#pragma unroll
    for (int i = 0; i < 10; i++)
#pragma unroll
        for (int j = 0; j < 5; j++)
            sW[(mt * 10 + i) * NG + n + 32 * j] = acc[i][j];
    __syncthreads();

    for (int p = tid; p < WW * FF; p += 128) {
        int x = p / FF, c = p % FF;
        float zi = sW[x * NG + c];
        float zf = sW[x * NG + 40 + c];
        float zg = sW[x * NG + 80 + c];
        float zo = sW[x * NG + 120 + c];
        int off = ((b * HH + y) * WW + x) * FF + c;
        float cp = first ? 0.0f : cst[off];
        float cn = hsig(zf) * cp + hsig(zi) * tanhf(zg);
        float hn = hsig(zo) * tanhf(cn);
        cst[off] = cn;
        hout[off] = hn;
        float s  = bng[c] * rsqrtf(bnv[c] + 1e-3f);
        float tt = bnb[c] - bnm[c] * s;
        yout[(((b * TT + t) * HH + y) * WW + x) * FF + c] = hn * s + tt;
    }
}

// ---------------------------------------------------------------------------
// Conv3D head: 3x3x3 over (T,H,W), 40 -> 1 channel, + sigmoid.
// Grid (HH, TT, BB): block handles one output row (b,t,y), 160 threads:
// thread = (x, channel-group of 10), partials reduced in smem.
// ---------------------------------------------------------------------------
__global__ __launch_bounds__(160) void conv3d_kernel(
    const float* __restrict__ in,   // [B,T,H,W,F]
    const float* __restrict__ w3,   // [3,3,3,F,1] -> [27*F]
    const float* __restrict__ b3,   // [1]
    float* __restrict__ out)        // [B,T,H,W]
{
    extern __shared__ float smem[];
    float* sT  = smem;                 // [9][42][40]
    float* sWc = smem + 9 * 42 * 40;   // [1080]
    float* sP  = sWc + 27 * 40;        // [4][40]

    const int tid = threadIdx.x;
    const int y = blockIdx.x, t = blockIdx.y, b = blockIdx.z;

    for (int i = tid; i < 9 * 42 * 40; i += 160) sT[i] = 0.0f;
    for (int i = tid; i < 27 * 40; i += 160) sWc[i] = w3[i];
    __syncthreads();

    for (int i = tid; i < 9 * 40 * 10; i += 160) {
        int c4 = i % 10;
        int rest = i / 10;
        int x = rest % 40;
        int rr = rest / 40;            // 0..8 = dt*3+dy
        int dt = rr / 3, dy = rr % 3;
        int gt = t + dt - 1, gy = y + dy - 1;
        if (gt >= 0 && gt < TT && gy >= 0 && gy < HH) {
            float4 v = *(const float4*)&in[(((b * TT + gt) * HH + gy) * WW + x) * FF + c4 * 4];
            *(float4*)&sT[(rr * 42 + x + 1) * 40 + c4 * 4] = v;
        }
    }
    __syncthreads();

    const int x  = tid % 40;
    const int cg = tid / 40;           // 0..3 -> channels cg*10..cg*10+9
    float s = 0.0f;
#pragma unroll 1
    for (int rr = 0; rr < 9; rr++) {
#pragma unroll
        for (int dx = 0; dx < 3; dx++) {
            const float* ip = &sT[(rr * 42 + x + dx) * 40 + cg * 10];
            const float* wp = &sWc[(rr * 3 + dx) * 40 + cg * 10];
#pragma unroll
            for (int c = 0; c < 10; c++) s += ip[c] * wp[c];
        }
    }
    sP[cg * 40 + x] = s;
    __syncthreads();
    if (tid < 40) {
        float v = sP[tid] + sP[40 + tid] + sP[80 + tid] + sP[120 + tid] + b3[0];
        out[((b * TT + t) * HH + y) * WW + tid] = 1.0f / (1.0f + expf(-v));
    }
}

// ---------------------------------------------------------------------------
// kernel_launch: 4 layers x 32 timesteps (sequential) + conv3d head.
// Graph-capturable: kernel launches + cudaFuncSetAttribute only.
// ---------------------------------------------------------------------------
extern "C" void kernel_launch(void* const* d_in, const int* in_sizes, int n_in,
                              void* d_out, int out_size)
{
    (void)in_sizes; (void)n_in; (void)out_size;

    const float* inp = (const float*)d_in[0];
    const float* W3  = (const float*)d_in[29];
    const float* b3  = (const float*)d_in[30];

    float *seq0, *seq1, *hb, *cb;
    cudaGetSymbolAddress((void**)&seq0, g_seq0);
    cudaGetSymbolAddress((void**)&seq1, g_seq1);
    cudaGetSymbolAddress((void**)&hb,   g_hbuf);
    cudaGetSymbolAddress((void**)&cb,   g_cbuf);
    float* hbuf[2] = { hb, hb + BB * HH * WW * FF };
    float* seqs[2] = { seq0, seq1 };

    const int smem40 = (3 * 42 * 80 + 40 * NG) * 4;          // 65920 B
    const int smem1  = (3 * 42 * 44 + 40 * NG) * 4;          // 47776 B
    const int smem3d = (9 * 42 * 40 + 27 * 40 + 4 * 40) * 4; // 65440 B

    cudaFuncSetAttribute(lstm_step<1>,  cudaFuncAttributeMaxDynamicSharedMemorySize, smem1);
    cudaFuncSetAttribute(lstm_step<40>, cudaFuncAttributeMaxDynamicSharedMemorySize, smem40);
    cudaFuncSetAttribute(conv3d_kernel, cudaFuncAttributeMaxDynamicSharedMemorySize, smem3d);

    const float* lin = inp;
    for (int l = 0; l < 4; l++) {
        const float* Wx  = (const float*)d_in[1 + 7 * l];
        const float* Wh  = (const float*)d_in[2 + 7 * l];
        const float* bia = (const float*)d_in[3 + 7 * l];
        const float* g   = (const float*)d_in[4 + 7 * l];
        const float* be  = (const float*)d_in[5 + 7 * l];
        const float* mu  = (const float*)d_in[6 + 7 * l];
        const float* v   = (const float*)d_in[7 + 7 * l];
        float* lout = seqs[l & 1];

        for (int t = 0; t < TT; t++) {
            const float* hi = hbuf[t & 1];
            float* ho = hbuf[(t + 1) & 1];
            int first = (t == 0);
            if (l == 0)
                lstm_step<1><<<dim3(HH, BB), 128, smem1>>>(
                    lin, hi, ho, cb, Wx, Wh, bia, g, be, mu, v, lout, t, first);
            else
                lstm_step<40><<<dim3(HH, BB), 128, smem40>>>(
                    lin, hi, ho, cb, Wx, Wh, bia, g, be, mu, v, lout, t, first);
        }
        lin = lout;
    }

    conv3d_kernel<<<dim3(HH, TT, BB), 160, smem3d>>>(lin, W3, b3, (float*)d_out);
}

// round 5
// speedup vs baseline: 1.1704x; 1.1704x over previous
#include <cuda_runtime.h>
#include <math.h>

// Problem constants
#define BB 16
#define TT 32
#define HH 40
#define WW 40
#define FF 40
#define NG 160              // 4*F gate channels
#define SEQN (BB*TT*HH*WW*FF)
#define STN  (BB*HH*WW*FF)

// ---------------------------------------------------------------------------
// Static device scratch (no cudaMalloc allowed).
//   g_seq[l] : output sequence of layer l (BN applied)  [B,T,H,W,F]
//   g_h[l][p]: double-buffered hidden state per layer   [B,H,W,F]
//   g_c[l]   : cell state per layer (in-place update)   [B,H,W,F]
// ---------------------------------------------------------------------------
__device__ float g_seq[4][SEQN];
__device__ float g_h[4][2][STN];
__device__ float g_c[4][STN];

__device__ __forceinline__ float hsig(float x) {
    return fminf(fmaxf(0.2f * x + 0.5f, 0.0f), 1.0f);
}

// ---------------------------------------------------------------------------
// One ConvLSTM timestep tile for one (layer, t): block = one image row (b,y).
// GEMM: M=40 px, N=160 gates, K=9*(CIN+FF). 128 threads, thread tile 10px x 5ch.
// SMEM: sIn[3][42][C2P] input tile (x ++ h, zero halo)  = 40320 B (CIN=40)
//       sW [CHUNK=20 x 160] weight chunk                =  12800 B
//       z scratch overlaid on sIn after GEMM.
// Total 53120 B -> 4 CTAs/SM (RF also allows exactly 4 at 128 regs).
// ---------------------------------------------------------------------------
template <int CIN>
__device__ __forceinline__ void lstm_tile(
    const float* __restrict__ xseq,   // [B,T,H,W,CIN]
    const float* __restrict__ hin,    // [B,H,W,F]
    float* __restrict__ hout,         // [B,H,W,F]
    float* __restrict__ cst,          // [B,H,W,F] in/out
    const float* __restrict__ Wx,     // [9,CIN,160]
    const float* __restrict__ Wh,     // [9,F,160]
    const float* __restrict__ bias,   // [160]
    const float* __restrict__ bng, const float* __restrict__ bnb,
    const float* __restrict__ bnm, const float* __restrict__ bnv,
    float* __restrict__ yout,         // [B,T,H,W,F]
    int t, int first)
{
    constexpr int HOFF  = (CIN + 3) & ~3;   // h channels start (4 or 40)
    constexpr int C2P   = HOFF + FF;        // padded concat channels (44 or 80)
    constexpr int INROW = 42;               // 40 + halo
    constexpr int CHUNK = 20;               // K-rows of weights staged at once

    extern __shared__ float smem[];
    float* sIn = smem;                      // [3][INROW][C2P]
    float* sW  = smem + 3 * INROW * C2P;    // [CHUNK*160]

    const int tid = threadIdx.x;
    const int y   = blockIdx.x;
    const int b   = blockIdx.y;
    const int n   = tid & 31;               // base output channel
    const int mt  = tid >> 5;               // pixel group (10 px)

    // ---- zero input tile (halo + padding) ----
    for (int i = tid; i < 3 * INROW * C2P; i += 128) sIn[i] = 0.0f;
    __syncthreads();

    // ---- fill x part ----
    if (CIN == 1) {
        for (int i = tid; i < 3 * WW; i += 128) {
            int r = i / WW, x = i % WW;
            int gy = y + r - 1;
            if (gy >= 0 && gy < HH)
                sIn[(r * INROW + x + 1) * C2P] =
                    xseq[((b * TT + t) * HH + gy) * WW + x];
        }
    } else {
        constexpr int NC4 = CIN / 4;
        for (int i = tid; i < 3 * WW * NC4; i += 128) {
            int c4 = i % NC4;
            int rest = i / NC4;
            int x = rest % WW, r = rest / WW;
            int gy = y + r - 1;
            if (gy >= 0 && gy < HH) {
                float4 v = *(const float4*)&xseq[(((b * TT + t) * HH + gy) * WW + x) * CIN + c4 * 4];
                *(float4*)&sIn[(r * INROW + x + 1) * C2P + c4 * 4] = v;
            }
        }
    }

    // ---- fill h part (h==0 at t==0) ----
    if (!first) {
        for (int i = tid; i < 3 * WW * (FF / 4); i += 128) {
            int c4 = i % (FF / 4);
            int rest = i / (FF / 4);
            int x = rest % WW, r = rest / WW;
            int gy = y + r - 1;
            if (gy >= 0 && gy < HH) {
                float4 v = *(const float4*)&hin[((b * HH + gy) * WW + x) * FF + c4 * 4];
                *(float4*)&sIn[(r * INROW + x + 1) * C2P + HOFF + c4 * 4] = v;
            }
        }
    }

    // ---- accumulators = bias ----
    float acc[10][5];
#pragma unroll
    for (int j = 0; j < 5; j++) {
        float bj = bias[n + 32 * j];
#pragma unroll
        for (int i = 0; i < 10; i++) acc[i][j] = bj;
    }

    // ---- main loop: 9 taps x {x-chunk, h-chunk}, weights staged 20 rows ----
#pragma unroll 1
    for (int tap = 0; tap < 9; ++tap) {
        const int dy = tap / 3, dx = tap % 3;
#pragma unroll 1
        for (int part = 0; part < 2; ++part) {
            if (part == 1 && first) continue;   // uniform across block
            const float* src = (part == 0) ? (Wx + tap * CIN * NG) : (Wh + tap * FF * NG);
            const int len    = (part == 0) ? CIN : FF;
            const int cbase  = (part == 0) ? 0 : HOFF;

#pragma unroll 1
            for (int k0 = 0; k0 < len; k0 += CHUNK) {
                const int cl = (len - k0 < CHUNK) ? (len - k0) : CHUNK;

                __syncthreads();   // prev chunk consumed / sIn fill done
                for (int p = tid; p < cl * (NG / 4); p += 128)
                    ((float4*)sW)[p] = ((const float4*)(src + k0 * NG))[p];
                __syncthreads();

                const float* abase = sIn + (dy * INROW + dx) * C2P + cbase + k0;
                const int kmain = cl & ~3;

#pragma unroll 1
                for (int kk = 0; kk < kmain; kk += 4) {
                    float4 a[10];
#pragma unroll
                    for (int i = 0; i < 10; i++)
                        a[i] = *(const float4*)(abase + (mt * 10 + i) * C2P + kk);
#pragma unroll
                    for (int l = 0; l < 4; l++) {
                        float bv[5];
#pragma unroll
                        for (int j = 0; j < 5; j++)
                            bv[j] = sW[(kk + l) * NG + n + 32 * j];
#pragma unroll
                        for (int i = 0; i < 10; i++) {
                            float av = (l == 0) ? a[i].x : (l == 1) ? a[i].y
                                     : (l == 2) ? a[i].z : a[i].w;
#pragma unroll
                            for (int j = 0; j < 5; j++) acc[i][j] += av * bv[j];
                        }
                    }
                }
                for (int kk = kmain; kk < cl; kk++) {   // remainder (CIN=1)
                    float bv[5];
#pragma unroll
                    for (int j = 0; j < 5; j++)
                        bv[j] = sW[kk * NG + n + 32 * j];
#pragma unroll
                    for (int i = 0; i < 10; i++) {
                        float av = abase[(mt * 10 + i) * C2P + kk];
#pragma unroll
                        for (int j = 0; j < 5; j++) acc[i][j] += av * bv[j];
                    }
                }
            }
        }
    }

    // ---- z into smem base (sIn is dead), then gate math ----
    __syncthreads();
    float* sZ = smem;   // 40*160 floats = 25.6KB <= sIn+sW region
#pragma unroll
    for (int i = 0; i < 10; i++)
#pragma unroll
        for (int j = 0; j < 5; j++)
            sZ[(mt * 10 + i) * NG + n + 32 * j] = acc[i][j];
    __syncthreads();

    for (int p = tid; p < WW * FF; p += 128) {
        int x = p / FF, c = p % FF;
        float zi = sZ[x * NG + c];
        float zf = sZ[x * NG + 40 + c];
        float zg = sZ[x * NG + 80 + c];
        float zo = sZ[x * NG + 120 + c];
        int off = ((b * HH + y) * WW + x) * FF + c;
        float cp = first ? 0.0f : cst[off];
        float cn = hsig(zf) * cp + hsig(zi) * tanhf(zg);
        float hn = hsig(zo) * tanhf(cn);
        cst[off]  = cn;
        hout[off] = hn;
        float s  = bng[c] * rsqrtf(bnv[c] + 1e-3f);
        float tt = bnb[c] - bnm[c] * s;
        yout[(((b * TT + t) * HH + y) * WW + x) * FF + c] = hn * s + tt;
    }
}

// ---------------------------------------------------------------------------
// Wavefront kernel: one launch covers all active (layer, t = wave - layer).
// Grid: (HH, BB, n_active_layers).
// ---------------------------------------------------------------------------
struct WaveP {
    const float* in[4];
    float*       out[4];
    const float* hin[4];
    float*       hout[4];
    float*       c[4];
    const float* Wx[4]; const float* Wh[4]; const float* bias[4];
    const float* g[4];  const float* be[4]; const float* mu[4]; const float* v[4];
    int wave, l0;
};

__global__ __launch_bounds__(128, 4) void wave_kernel(WaveP P)
{
    const int l = P.l0 + blockIdx.z;
    const int t = P.wave - l;
    const int first = (t == 0);
    if (l == 0)
        lstm_tile<1>(P.in[0], P.hin[0], P.hout[0], P.c[0],
                     P.Wx[0], P.Wh[0], P.bias[0],
                     P.g[0], P.be[0], P.mu[0], P.v[0],
                     P.out[0], t, first);
    else
        lstm_tile<40>(P.in[l], P.hin[l], P.hout[l], P.c[l],
                      P.Wx[l], P.Wh[l], P.bias[l],
                      P.g[l], P.be[l], P.mu[l], P.v[l],
                      P.out[l], t, first);
}

// ---------------------------------------------------------------------------
// Conv3D head: 3x3x3 over (T,H,W), 40 -> 1 channel, + sigmoid.
// ---------------------------------------------------------------------------
__global__ __launch_bounds__(160) void conv3d_kernel(
    const float* __restrict__ in,   // [B,T,H,W,F]
    const float* __restrict__ w3,   // [27*F]
    const float* __restrict__ b3,   // [1]
    float* __restrict__ out)        // [B,T,H,W]
{
    extern __shared__ float smem[];
    float* sT  = smem;                 // [9][42][40]
    float* sWc = smem + 9 * 42 * 40;   // [1080]
    float* sP  = sWc + 27 * 40;        // [4][40]

    const int tid = threadIdx.x;
    const int y = blockIdx.x, t = blockIdx.y, b = blockIdx.z;

    for (int i = tid; i < 9 * 42 * 40; i += 160) sT[i] = 0.0f;
    for (int i = tid; i < 27 * 40; i += 160) sWc[i] = w3[i];
    __syncthreads();

    for (int i = tid; i < 9 * 40 * 10; i += 160) {
        int c4 = i % 10;
        int rest = i / 10;
        int x = rest % 40;
        int rr = rest / 40;            // dt*3+dy
        int dt = rr / 3, dy = rr % 3;
        int gt = t + dt - 1, gy = y + dy - 1;
        if (gt >= 0 && gt < TT && gy >= 0 && gy < HH) {
            float4 v = *(const float4*)&in[(((b * TT + gt) * HH + gy) * WW + x) * FF + c4 * 4];
            *(float4*)&sT[(rr * 42 + x + 1) * 40 + c4 * 4] = v;
        }
    }
    __syncthreads();

    const int x  = tid % 40;
    const int cg = tid / 40;
    float s = 0.0f;
#pragma unroll 1
    for (int rr = 0; rr < 9; rr++) {
#pragma unroll
        for (int dx = 0; dx < 3; dx++) {
            const float* ip = &sT[(rr * 42 + x + dx) * 40 + cg * 10];
            const float* wp = &sWc[(rr * 3 + dx) * 40 + cg * 10];
#pragma unroll
            for (int c = 0; c < 10; c++) s += ip[c] * wp[c];
        }
    }
    sP[cg * 40 + x] = s;
    __syncthreads();
    if (tid < 40) {
        float v = sP[tid] + sP[40 + tid] + sP[80 + tid] + sP[120 + tid] + b3[0];
        out[((b * TT + t) * HH + y) * WW + tid] = 1.0f / (1.0f + expf(-v));
    }
}

// ---------------------------------------------------------------------------
// kernel_launch: 35 wavefront launches + conv3d head. Graph-capturable.
// ---------------------------------------------------------------------------
extern "C" void kernel_launch(void* const* d_in, const int* in_sizes, int n_in,
                              void* d_out, int out_size)
{
    (void)in_sizes; (void)n_in; (void)out_size;

    const float* inp = (const float*)d_in[0];
    const float* W3  = (const float*)d_in[29];
    const float* b3  = (const float*)d_in[30];

    float *seqbase, *hbase, *cbase;
    cudaGetSymbolAddress((void**)&seqbase, g_seq);
    cudaGetSymbolAddress((void**)&hbase,   g_h);
    cudaGetSymbolAddress((void**)&cbase,   g_c);

    float* seqp[4];
    float* hp[4][2];
    float* cp[4];
    for (int l = 0; l < 4; l++) {
        seqp[l]  = seqbase + (size_t)l * SEQN;
        hp[l][0] = hbase + ((size_t)l * 2 + 0) * STN;
        hp[l][1] = hbase + ((size_t)l * 2 + 1) * STN;
        cp[l]    = cbase + (size_t)l * STN;
    }

    const int SMEMW  = (3 * 42 * 80 + 20 * NG) * 4;            // 53120 B
    const int smem3d = (9 * 42 * 40 + 27 * 40 + 4 * 40) * 4;   // 65440 B

    cudaFuncSetAttribute(wave_kernel,   cudaFuncAttributeMaxDynamicSharedMemorySize, SMEMW);
    cudaFuncSetAttribute(conv3d_kernel, cudaFuncAttributeMaxDynamicSharedMemorySize, smem3d);

    for (int wave = 0; wave < TT + 3; wave++) {
        int l0 = wave - (TT - 1); if (l0 < 0) l0 = 0;
        int l1 = wave < 3 ? wave : 3;

        WaveP P;
        for (int l = 0; l < 4; l++) {
            int t = wave - l;
            int tc = t < 0 ? 0 : (t > TT - 1 ? TT - 1 : t);
            P.in[l]   = (l == 0) ? inp : seqp[l - 1];
            P.out[l]  = seqp[l];
            P.hin[l]  = hp[l][tc & 1];
            P.hout[l] = hp[l][(tc + 1) & 1];
            P.c[l]    = cp[l];
            P.Wx[l]   = (const float*)d_in[1 + 7 * l];
            P.Wh[l]   = (const float*)d_in[2 + 7 * l];
            P.bias[l] = (const float*)d_in[3 + 7 * l];
            P.g[l]    = (const float*)d_in[4 + 7 * l];
            P.be[l]   = (const float*)d_in[5 + 7 * l];
            P.mu[l]   = (const float*)d_in[6 + 7 * l];
            P.v[l]    = (const float*)d_in[7 + 7 * l];
        }
        P.wave = wave;
        P.l0   = l0;

        wave_kernel<<<dim3(HH, BB, l1 - l0 + 1), 128, SMEMW>>>(P);
    }

    conv3d_kernel<<<dim3(HH, TT, BB), 160, smem3d>>>(seqp[3], W3, b3, (float*)d_out);
}

// round 6
// speedup vs baseline: 1.1721x; 1.0015x over previous
#include <cuda_runtime.h>
#include <math.h>

// Problem constants
#define BB 16
#define TT 32
#define HH 40
#define WW 40
#define FF 40
#define NG 160              // 4*F gate channels
#define SEQN (BB*TT*HH*WW*FF)
#define STN  (BB*HH*WW*FF)

// ---------------------------------------------------------------------------
// Static device scratch (no cudaMalloc allowed).
//   g_seq[l] : output sequence of layer l (BN applied)  [B,T,H,W,F]
//   g_h[l][p]: double-buffered hidden state per layer   [B,H,W,F]
//   g_c[l]   : cell state per layer (in-place update)   [B,H,W,F]
// ---------------------------------------------------------------------------
__device__ float g_seq[4][SEQN];
__device__ float g_h[4][2][STN];
__device__ float g_c[4][STN];

__device__ __forceinline__ float hsig(float x) {
    return fminf(fmaxf(0.2f * x + 0.5f, 0.0f), 1.0f);
}

// ---------------------------------------------------------------------------
// One ConvLSTM timestep tile for one (layer, t): block = one image row (b,y).
// GEMM: M=40 px, N=160 gates, K=9*(CIN+FF). 128 threads, thread tile 10px x 5ch.
// SMEM: sIn[3][42][C2P] input tile (x ++ h, zero halo)  = 40320 B (CIN=40)
//       sW [CHUNK=20 x 160] weight chunk                =  12800 B
//       z scratch overlaid on sIn after GEMM.
// Total 53120 B -> 4 CTAs/SM (RF also allows exactly 4 at 128 regs).
// ---------------------------------------------------------------------------
template <int CIN>
__device__ __forceinline__ void lstm_tile(
    const float* __restrict__ xseq,   // [B,T,H,W,CIN]
    const float* __restrict__ hin,    // [B,H,W,F]
    float* __restrict__ hout,         // [B,H,W,F]
    float* __restrict__ cst,          // [B,H,W,F] in/out
    const float* __restrict__ Wx,     // [9,CIN,160]
    const float* __restrict__ Wh,     // [9,F,160]
    const float* __restrict__ bias,   // [160]
    const float* __restrict__ bng, const float* __restrict__ bnb,
    const float* __restrict__ bnm, const float* __restrict__ bnv,
    float* __restrict__ yout,         // [B,T,H,W,F]
    int t, int first)
{
    constexpr int HOFF  = (CIN + 3) & ~3;   // h channels start (4 or 40)
    constexpr int C2P   = HOFF + FF;        // padded concat channels (44 or 80)
    constexpr int INROW = 42;               // 40 + halo
    constexpr int CHUNK = 20;               // K-rows of weights staged at once

    extern __shared__ float smem[];
    float* sIn = smem;                      // [3][INROW][C2P]
    float* sW  = smem + 3 * INROW * C2P;    // [CHUNK*160]

    const int tid = threadIdx.x;
    const int y   = blockIdx.x;
    const int b   = blockIdx.y;
    const int n   = tid & 31;               // base output channel
    const int mt  = tid >> 5;               // pixel group (10 px)

    // ---- zero input tile (halo + padding) ----
    for (int i = tid; i < 3 * INROW * C2P; i += 128) sIn[i] = 0.0f;
    __syncthreads();

    // ---- fill x part ----
    if (CIN == 1) {
        for (int i = tid; i < 3 * WW; i += 128) {
            int r = i / WW, x = i % WW;
            int gy = y + r - 1;
            if (gy >= 0 && gy < HH)
                sIn[(r * INROW + x + 1) * C2P] =
                    xseq[((b * TT + t) * HH + gy) * WW + x];
        }
    } else {
        constexpr int NC4 = CIN / 4;
        for (int i = tid; i < 3 * WW * NC4; i += 128) {
            int c4 = i % NC4;
            int rest = i / NC4;
            int x = rest % WW, r = rest / WW;
            int gy = y + r - 1;
            if (gy >= 0 && gy < HH) {
                float4 v = *(const float4*)&xseq[(((b * TT + t) * HH + gy) * WW + x) * CIN + c4 * 4];
                *(float4*)&sIn[(r * INROW + x + 1) * C2P + c4 * 4] = v;
            }
        }
    }

    // ---- fill h part (h==0 at t==0) ----
    if (!first) {
        for (int i = tid; i < 3 * WW * (FF / 4); i += 128) {
            int c4 = i % (FF / 4);
            int rest = i / (FF / 4);
            int x = rest % WW, r = rest / WW;
            int gy = y + r - 1;
            if (gy >= 0 && gy < HH) {
                float4 v = *(const float4*)&hin[((b * HH + gy) * WW + x) * FF + c4 * 4];
                *(float4*)&sIn[(r * INROW + x + 1) * C2P + HOFF + c4 * 4] = v;
            }
        }
    }

    // ---- accumulators = bias ----
    float acc[10][5];
#pragma unroll
    for (int j = 0; j < 5; j++) {
        float bj = bias[n + 32 * j];
#pragma unroll
        for (int i = 0; i < 10; i++) acc[i][j] = bj;
    }

    // ---- main loop: 9 taps x {x-chunk, h-chunk}, weights staged 20 rows ----
#pragma unroll 1
    for (int tap = 0; tap < 9; ++tap) {
        const int dy = tap / 3, dx = tap % 3;
#pragma unroll 1
        for (int part = 0; part < 2; ++part) {
            if (part == 1 && first) continue;   // uniform across block
            const float* src = (part == 0) ? (Wx + tap * CIN * NG) : (Wh + tap * FF * NG);
            const int len    = (part == 0) ? CIN : FF;
            const int cbase  = (part == 0) ? 0 : HOFF;

#pragma unroll 1
            for (int k0 = 0; k0 < len; k0 += CHUNK) {
                const int cl = (len - k0 < CHUNK) ? (len - k0) : CHUNK;

                __syncthreads();   // prev chunk consumed / sIn fill done
                for (int p = tid; p < cl * (NG / 4); p += 128)
                    ((float4*)sW)[p] = ((const float4*)(src + k0 * NG))[p];
                __syncthreads();

                const float* abase = sIn + (dy * INROW + dx) * C2P + cbase + k0;
                const int kmain = cl & ~3;

#pragma unroll 1
                for (int kk = 0; kk < kmain; kk += 4) {
                    float4 a[10];
#pragma unroll
                    for (int i = 0; i < 10; i++)
                        a[i] = *(const float4*)(abase + (mt * 10 + i) * C2P + kk);
#pragma unroll
                    for (int l = 0; l < 4; l++) {
                        float bv[5];
#pragma unroll
                        for (int j = 0; j < 5; j++)
                            bv[j] = sW[(kk + l) * NG + n + 32 * j];
#pragma unroll
                        for (int i = 0; i < 10; i++) {
                            float av = (l == 0) ? a[i].x : (l == 1) ? a[i].y
                                     : (l == 2) ? a[i].z : a[i].w;
#pragma unroll
                            for (int j = 0; j < 5; j++) acc[i][j] += av * bv[j];
                        }
                    }
                }
                for (int kk = kmain; kk < cl; kk++) {   // remainder (CIN=1)
                    float bv[5];
#pragma unroll
                    for (int j = 0; j < 5; j++)
                        bv[j] = sW[kk * NG + n + 32 * j];
#pragma unroll
                    for (int i = 0; i < 10; i++) {
                        float av = abase[(mt * 10 + i) * C2P + kk];
#pragma unroll
                        for (int j = 0; j < 5; j++) acc[i][j] += av * bv[j];
                    }
                }
            }
        }
    }

    // ---- z into smem base (sIn is dead), then gate math ----
    __syncthreads();
    float* sZ = smem;   // 40*160 floats = 25.6KB <= sIn+sW region
#pragma unroll
    for (int i = 0; i < 10; i++)
#pragma unroll
        for (int j = 0; j < 5; j++)
            sZ[(mt * 10 + i) * NG + n + 32 * j] = acc[i][j];
    __syncthreads();

    for (int p = tid; p < WW * FF; p += 128) {
        int x = p / FF, c = p % FF;
        float zi = sZ[x * NG + c];
        float zf = sZ[x * NG + 40 + c];
        float zg = sZ[x * NG + 80 + c];
        float zo = sZ[x * NG + 120 + c];
        int off = ((b * HH + y) * WW + x) * FF + c;
        float cp = first ? 0.0f : cst[off];
        float cn = hsig(zf) * cp + hsig(zi) * tanhf(zg);
        float hn = hsig(zo) * tanhf(cn);
        cst[off]  = cn;
        hout[off] = hn;
        float s  = bng[c] * rsqrtf(bnv[c] + 1e-3f);
        float tt = bnb[c] - bnm[c] * s;
        yout[(((b * TT + t) * HH + y) * WW + x) * FF + c] = hn * s + tt;
    }
}

// ---------------------------------------------------------------------------
// Wavefront kernel: one launch covers all active (layer, t = wave - layer).
// Grid: (HH, BB, n_active_layers).
// ---------------------------------------------------------------------------
struct WaveP {
    const float* in[4];
    float*       out[4];
    const float* hin[4];
    float*       hout[4];
    float*       c[4];
    const float* Wx[4]; const float* Wh[4]; const float* bias[4];
    const float* g[4];  const float* be[4]; const float* mu[4]; const float* v[4];
    int wave, l0;
};

__global__ __launch_bounds__(128, 4) void wave_kernel(WaveP P)
{
    const int l = P.l0 + blockIdx.z;
    const int t = P.wave - l;
    const int first = (t == 0);
    if (l == 0)
        lstm_tile<1>(P.in[0], P.hin[0], P.hout[0], P.c[0],
                     P.Wx[0], P.Wh[0], P.bias[0],
                     P.g[0], P.be[0], P.mu[0], P.v[0],
                     P.out[0], t, first);
    else
        lstm_tile<40>(P.in[l], P.hin[l], P.hout[l], P.c[l],
                      P.Wx[l], P.Wh[l], P.bias[l],
                      P.g[l], P.be[l], P.mu[l], P.v[l],
                      P.out[l], t, first);
}

// ---------------------------------------------------------------------------
// Conv3D head: 3x3x3 over (T,H,W), 40 -> 1 channel, + sigmoid.
// ---------------------------------------------------------------------------
__global__ __launch_bounds__(160) void conv3d_kernel(
    const float* __restrict__ in,   // [B,T,H,W,F]
    const float* __restrict__ w3,   // [27*F]
    const float* __restrict__ b3,   // [1]
    float* __restrict__ out)        // [B,T,H,W]
{
    extern __shared__ float smem[];
    float* sT  = smem;                 // [9][42][40]
    float* sWc = smem + 9 * 42 * 40;   // [1080]
    float* sP  = sWc + 27 * 40;        // [4][40]

    const int tid = threadIdx.x;
    const int y = blockIdx.x, t = blockIdx.y, b = blockIdx.z;

    for (int i = tid; i < 9 * 42 * 40; i += 160) sT[i] = 0.0f;
    for (int i = tid; i < 27 * 40; i += 160) sWc[i] = w3[i];
    __syncthreads();

    for (int i = tid; i < 9 * 40 * 10; i += 160) {
        int c4 = i % 10;
        int rest = i / 10;
        int x = rest % 40;
        int rr = rest / 40;            // dt*3+dy
        int dt = rr / 3, dy = rr % 3;
        int gt = t + dt - 1, gy = y + dy - 1;
        if (gt >= 0 && gt < TT && gy >= 0 && gy < HH) {
            float4 v = *(const float4*)&in[(((b * TT + gt) * HH + gy) * WW + x) * FF + c4 * 4];
            *(float4*)&sT[(rr * 42 + x + 1) * 40 + c4 * 4] = v;
        }
    }
    __syncthreads();

    const int x  = tid % 40;
    const int cg = tid / 40;
    float s = 0.0f;
#pragma unroll 1
    for (int rr = 0; rr < 9; rr++) {
#pragma unroll
        for (int dx = 0; dx < 3; dx++) {
            const float* ip = &sT[(rr * 42 + x + dx) * 40 + cg * 10];
            const float* wp = &sWc[(rr * 3 + dx) * 40 + cg * 10];
#pragma unroll
            for (int c = 0; c < 10; c++) s += ip[c] * wp[c];
        }
    }
    sP[cg * 40 + x] = s;
    __syncthreads();
    if (tid < 40) {
        float v = sP[tid] + sP[40 + tid] + sP[80 + tid] + sP[120 + tid] + b3[0];
        out[((b * TT + t) * HH + y) * WW + tid] = 1.0f / (1.0f + expf(-v));
    }
}

// ---------------------------------------------------------------------------
// kernel_launch: 35 wavefront launches + conv3d head. Graph-capturable.
// ---------------------------------------------------------------------------
extern "C" void kernel_launch(void* const* d_in, const int* in_sizes, int n_in,
                              void* d_out, int out_size)
{
    (void)in_sizes; (void)n_in; (void)out_size;

    const float* inp = (const float*)d_in[0];
    const float* W3  = (const float*)d_in[29];
    const float* b3  = (const float*)d_in[30];

    float *seqbase, *hbase, *cbase;
    cudaGetSymbolAddress((void**)&seqbase, g_seq);
    cudaGetSymbolAddress((void**)&hbase,   g_h);
    cudaGetSymbolAddress((void**)&cbase,   g_c);

    float* seqp[4];
    float* hp[4][2];
    float* cp[4];
    for (int l = 0; l < 4; l++) {
        seqp[l]  = seqbase + (size_t)l * SEQN;
        hp[l][0] = hbase + ((size_t)l * 2 + 0) * STN;
        hp[l][1] = hbase + ((size_t)l * 2 + 1) * STN;
        cp[l]    = cbase + (size_t)l * STN;
    }

    const int SMEMW  = (3 * 42 * 80 + 20 * NG) * 4;            // 53120 B
    const int smem3d = (9 * 42 * 40 + 27 * 40 + 4 * 40) * 4;   // 65440 B

    cudaFuncSetAttribute(wave_kernel,   cudaFuncAttributeMaxDynamicSharedMemorySize, SMEMW);
    cudaFuncSetAttribute(conv3d_kernel, cudaFuncAttributeMaxDynamicSharedMemorySize, smem3d);

    for (int wave = 0; wave < TT + 3; wave++) {
        int l0 = wave - (TT - 1); if (l0 < 0) l0 = 0;
        int l1 = wave < 3 ? wave : 3;

        WaveP P;
        for (int l = 0; l < 4; l++) {
            int t = wave - l;
            int tc = t < 0 ? 0 : (t > TT - 1 ? TT - 1 : t);
            P.in[l]   = (l == 0) ? inp : seqp[l - 1];
            P.out[l]  = seqp[l];
            P.hin[l]  = hp[l][tc & 1];
            P.hout[l] = hp[l][(tc + 1) & 1];
            P.c[l]    = cp[l];
            P.Wx[l]   = (const float*)d_in[1 + 7 * l];
            P.Wh[l]   = (const float*)d_in[2 + 7 * l];
            P.bias[l] = (const float*)d_in[3 + 7 * l];
            P.g[l]    = (const float*)d_in[4 + 7 * l];
            P.be[l]   = (const float*)d_in[5 + 7 * l];
            P.mu[l]   = (const float*)d_in[6 + 7 * l];
            P.v[l]    = (const float*)d_in[7 + 7 * l];
        }
        P.wave = wave;
        P.l0   = l0;

        wave_kernel<<<dim3(HH, BB, l1 - l0 + 1), 128, SMEMW>>>(P);
    }

    conv3d_kernel<<<dim3(HH, TT, BB), 160, smem3d>>>(seqp[3], W3, b3, (float*)d_out);
}